// round 2
// baseline (speedup 1.0000x reference)
#include <cuda_runtime.h>
#include <cuda_bf16.h>
#include <math.h>

#define D 128
#define MAX_NODES 50000
#define MAX_GRAPHS 500
#define BN_EPS 1e-5f

// ---------------- scratch (static device allocations are allowed) -------------
__device__ float g_agg [MAX_NODES * D];
__device__ float g_x1  [MAX_NODES * D];
__device__ float g_x2  [MAX_NODES * D];
__device__ float g_pool[MAX_GRAPHS * D];

// ---------------- edge scatter: agg[dst] += x[src] ---------------------------
__device__ __forceinline__ void red_add_v4(float4* p, float4 v) {
    asm volatile("red.global.add.v4.f32 [%0], {%1,%2,%3,%4};"
                 :: "l"(p), "f"(v.x), "f"(v.y), "f"(v.z), "f"(v.w) : "memory");
}

__global__ void scatter_kernel(const float* __restrict__ x,
                               const int* __restrict__ src,
                               const int* __restrict__ dst,
                               float* __restrict__ agg, int nEdges) {
    int gid  = blockIdx.x * blockDim.x + threadIdx.x;
    int e    = gid >> 5;
    int lane = gid & 31;
    if (e >= nEdges) return;
    int s = src[e];
    int d = dst[e];
    float4 v = ((const float4*)x)[s * (D / 4) + lane];
    red_add_v4(((float4*)agg) + d * (D / 4) + lane, v);
}

// ---------------- fused per-layer MLP: ------------------------------------
// h = x + agg ; t = relu(h@W1 + b1) ; y = t@W2 + b2 ; y = BN(y) ; x' = relu(y)
// block: 128 rows x 128 cols, 256 threads (16x16), 8x8 register tile per thread
#define SH_STRIDE 129
#define TILE_M 128

__global__ __launch_bounds__(256, 1)
void mlp_kernel(const float* __restrict__ xin,
                const float* __restrict__ agg,
                const float* __restrict__ W1, const float* __restrict__ b1,
                const float* __restrict__ W2, const float* __restrict__ b2,
                const float* __restrict__ bns, const float* __restrict__ bnb,
                const float* __restrict__ bnm, const float* __restrict__ bnv,
                float* __restrict__ xout, int nNodes) {
    extern __shared__ float smem[];
    float* shH = smem;                      // [128][129]
    float* shW = smem + TILE_M * SH_STRIDE; // [128][129]
    float* shT = smem + 2 * TILE_M * SH_STRIDE;

    int tid = threadIdx.x;
    int tx  = tid & 15;   // col group
    int ty  = tid >> 4;   // row group
    int row0 = blockIdx.x * TILE_M;

    // --- load h = x + agg and W1 into smem ---
    for (int idx4 = tid; idx4 < TILE_M * (D / 4); idx4 += 256) {
        int r  = idx4 >> 5;
        int c4 = (idx4 & 31) * 4;
        int gr = row0 + r;
        float4 hv = make_float4(0.f, 0.f, 0.f, 0.f);
        if (gr < nNodes) {
            float4 xv = ((const float4*)xin)[gr * (D / 4) + (idx4 & 31)];
            float4 av = ((const float4*)agg)[gr * (D / 4) + (idx4 & 31)];
            hv = make_float4(xv.x + av.x, xv.y + av.y, xv.z + av.z, xv.w + av.w);
        }
        shH[r * SH_STRIDE + c4 + 0] = hv.x;
        shH[r * SH_STRIDE + c4 + 1] = hv.y;
        shH[r * SH_STRIDE + c4 + 2] = hv.z;
        shH[r * SH_STRIDE + c4 + 3] = hv.w;

        float4 wv = ((const float4*)W1)[idx4];
        shW[r * SH_STRIDE + c4 + 0] = wv.x;
        shW[r * SH_STRIDE + c4 + 1] = wv.y;
        shW[r * SH_STRIDE + c4 + 2] = wv.z;
        shW[r * SH_STRIDE + c4 + 3] = wv.w;
    }
    __syncthreads();

    // --- GEMM 1: t = relu(h @ W1 + b1) ---
    float acc[8][8];
    #pragma unroll
    for (int i = 0; i < 8; i++)
        #pragma unroll
        for (int j = 0; j < 8; j++) acc[i][j] = 0.f;

    #pragma unroll 4
    for (int k = 0; k < D; k++) {
        float a[8], b[8];
        #pragma unroll
        for (int i = 0; i < 8; i++) a[i] = shH[(ty + 16 * i) * SH_STRIDE + k];
        #pragma unroll
        for (int j = 0; j < 8; j++) b[j] = shW[k * SH_STRIDE + tx + 16 * j];
        #pragma unroll
        for (int i = 0; i < 8; i++)
            #pragma unroll
            for (int j = 0; j < 8; j++) acc[i][j] += a[i] * b[j];
    }
    __syncthreads();   // all reads of shW(W1) done

    // epilogue 1 -> shT, and load W2 into shW
    {
        float bb[8];
        #pragma unroll
        for (int j = 0; j < 8; j++) bb[j] = b1[tx + 16 * j];
        #pragma unroll
        for (int i = 0; i < 8; i++)
            #pragma unroll
            for (int j = 0; j < 8; j++) {
                float v = acc[i][j] + bb[j];
                shT[(ty + 16 * i) * SH_STRIDE + tx + 16 * j] = v > 0.f ? v : 0.f;
            }
    }
    for (int idx4 = tid; idx4 < (D * D) / 4; idx4 += 256) {
        int r  = idx4 >> 5;
        int c4 = (idx4 & 31) * 4;
        float4 wv = ((const float4*)W2)[idx4];
        shW[r * SH_STRIDE + c4 + 0] = wv.x;
        shW[r * SH_STRIDE + c4 + 1] = wv.y;
        shW[r * SH_STRIDE + c4 + 2] = wv.z;
        shW[r * SH_STRIDE + c4 + 3] = wv.w;
    }
    __syncthreads();

    // --- GEMM 2: y = t @ W2 + b2 ---
    #pragma unroll
    for (int i = 0; i < 8; i++)
        #pragma unroll
        for (int j = 0; j < 8; j++) acc[i][j] = 0.f;

    #pragma unroll 4
    for (int k = 0; k < D; k++) {
        float a[8], b[8];
        #pragma unroll
        for (int i = 0; i < 8; i++) a[i] = shT[(ty + 16 * i) * SH_STRIDE + k];
        #pragma unroll
        for (int j = 0; j < 8; j++) b[j] = shW[k * SH_STRIDE + tx + 16 * j];
        #pragma unroll
        for (int i = 0; i < 8; i++)
            #pragma unroll
            for (int j = 0; j < 8; j++) acc[i][j] += a[i] * b[j];
    }

    // epilogue 2: bias + BN + relu -> xout
    {
        float bb[8], kk[8], mm[8], cc[8];
        #pragma unroll
        for (int j = 0; j < 8; j++) {
            int c = tx + 16 * j;
            bb[j] = b2[c];
            kk[j] = bns[c] * rsqrtf(bnv[c] + BN_EPS);
            mm[j] = bnm[c];
            cc[j] = bnb[c];
        }
        #pragma unroll
        for (int i = 0; i < 8; i++) {
            int gr = row0 + ty + 16 * i;
            if (gr < nNodes) {
                #pragma unroll
                for (int j = 0; j < 8; j++) {
                    int c = tx + 16 * j;
                    float v = acc[i][j] + bb[j];
                    v = (v - mm[j]) * kk[j] + cc[j];
                    xout[gr * D + c] = v > 0.f ? v : 0.f;
                }
            }
        }
    }
}

// ---------------- graph pooling: pool[batch[i]] += x[i] ----------------------
__global__ void pool_kernel(const float* __restrict__ x,
                            const int* __restrict__ batch,
                            float* __restrict__ pool, int nNodes) {
    int gid  = blockIdx.x * blockDim.x + threadIdx.x;
    int node = gid >> 5;
    int lane = gid & 31;
    if (node >= nNodes) return;
    int g = batch[node];
    float4 v = ((const float4*)x)[node * (D / 4) + lane];
    red_add_v4(((float4*)pool) + g * (D / 4) + lane, v);
}

// ---------------- head: sigmoid(relu(g@Wh1+bh1) @ Wh2 + bh2) -----------------
#define HID 64
#define NCLS 12
__global__ void head_kernel(const float* __restrict__ pool,
                            const float* __restrict__ Wh1, const float* __restrict__ bh1,
                            const float* __restrict__ Wh2, const float* __restrict__ bh2,
                            float* __restrict__ out, int nGraphs) {
    __shared__ float sg[D];
    __shared__ float sh1[HID];
    int g = blockIdx.x;
    if (g >= nGraphs) return;
    int tid = threadIdx.x;  // 64 threads
    sg[tid]       = pool[g * D + tid];
    sg[tid + HID] = pool[g * D + tid + HID];
    __syncthreads();
    float a = bh1[tid];
    #pragma unroll 4
    for (int k = 0; k < D; k++) a += sg[k] * Wh1[k * HID + tid];
    sh1[tid] = a > 0.f ? a : 0.f;
    __syncthreads();
    if (tid < NCLS) {
        float o = bh2[tid];
        #pragma unroll
        for (int k = 0; k < HID; k++) o += sh1[k] * Wh2[k * NCLS + tid];
        out[g * NCLS + tid] = 1.f / (1.f + expf(-o));
    }
}

// ---------------- launcher ---------------------------------------------------
extern "C" void kernel_launch(void* const* d_in, const int* in_sizes, int n_in,
                              void* d_out, int out_size) {
    const float* x     = (const float*)d_in[0];
    const int*   ei    = (const int*)d_in[1];     // int32 (JAX x64 disabled)
    const int*   batch = (const int*)d_in[2];
    const float* W1    = (const float*)d_in[3];
    const float* b1    = (const float*)d_in[4];
    const float* W2    = (const float*)d_in[5];
    const float* b2    = (const float*)d_in[6];
    const float* bns   = (const float*)d_in[7];
    const float* bnb   = (const float*)d_in[8];
    const float* bnm   = (const float*)d_in[9];
    const float* bnv   = (const float*)d_in[10];
    const float* Wh1   = (const float*)d_in[11];
    const float* bh1   = (const float*)d_in[12];
    const float* Wh2   = (const float*)d_in[13];
    const float* bh2   = (const float*)d_in[14];
    float* out = (float*)d_out;

    int nNodes  = in_sizes[0] / D;
    int nEdges  = in_sizes[1] / 2;
    int nGraphs = out_size / NCLS;

    const int* src = ei;
    const int* dst = ei + nEdges;

    float *agg, *x1, *x2, *pool;
    cudaGetSymbolAddress((void**)&agg,  g_agg);
    cudaGetSymbolAddress((void**)&x1,   g_x1);
    cudaGetSymbolAddress((void**)&x2,   g_x2);
    cudaGetSymbolAddress((void**)&pool, g_pool);

    size_t smemBytes = 3 * TILE_M * SH_STRIDE * sizeof(float); // 198144 B
    cudaFuncSetAttribute(mlp_kernel, cudaFuncAttributeMaxDynamicSharedMemorySize,
                         (int)smemBytes);

    int scatterBlocks = (nEdges * 32 + 255) / 256;
    int mlpBlocks     = (nNodes + TILE_M - 1) / TILE_M;
    int poolBlocks    = (nNodes * 32 + 255) / 256;

    const float* xs[4] = { x, x1, x2, x1 };
    float*       xd[3] = { x1, x2, x1 };

    for (int l = 0; l < 3; l++) {
        cudaMemsetAsync(agg, 0, (size_t)nNodes * D * sizeof(float));
        scatter_kernel<<<scatterBlocks, 256>>>(xs[l], src, dst, agg, nEdges);
        mlp_kernel<<<mlpBlocks, 256, smemBytes>>>(
            xs[l], agg,
            W1 + l * D * D, b1 + l * D,
            W2 + l * D * D, b2 + l * D,
            bns + l * D, bnb + l * D, bnm + l * D, bnv + l * D,
            xd[l], nNodes);
    }

    cudaMemsetAsync(pool, 0, (size_t)nGraphs * D * sizeof(float));
    pool_kernel<<<poolBlocks, 256>>>(xs[3], batch, pool, nNodes);
    head_kernel<<<nGraphs, HID>>>(pool, Wh1, bh1, Wh2, bh2, out, nGraphs);
}

// round 4
// speedup vs baseline: 1.3570x; 1.3570x over previous
#include <cuda_runtime.h>
#include <cuda_bf16.h>
#include <math.h>
#include <cstdint>

#define D 128
#define MAX_NODES 50000
#define MAX_GRAPHS 500
#define BN_EPS 1e-5f

// ---------------- scratch ----------------------------------------------------
__device__ float g_agg [MAX_NODES * D];
__device__ float g_x1  [MAX_NODES * D];
__device__ float g_x2  [MAX_NODES * D];
__device__ float g_pool[MAX_GRAPHS * D];
__device__ float g_w1t [3 * D * D];   // W1 transposed [n][k], tf32-rounded
__device__ float g_w2t [3 * D * D];

// ---------------- helpers ----------------------------------------------------
__device__ __forceinline__ float tf32r(float v) {
    float o;
    asm("cvt.rna.tf32.f32 %0, %1;" : "=f"(o) : "f"(v));
    return o;
}
__device__ __forceinline__ void red_add_v4(float4* p, float4 v) {
    asm volatile("red.global.add.v4.f32 [%0], {%1,%2,%3,%4};"
                 :: "l"(p), "f"(v.x), "f"(v.y), "f"(v.z), "f"(v.w) : "memory");
}
// mma.sync m16n8k8 tf32: D += A*B
__device__ __forceinline__ void mma_tf32(float* d, const uint32_t* a, const uint32_t* b) {
    asm volatile(
        "mma.sync.aligned.m16n8k8.row.col.f32.tf32.tf32.f32 "
        "{%0,%1,%2,%3}, {%4,%5,%6,%7}, {%8,%9}, {%0,%1,%2,%3};"
        : "+f"(d[0]), "+f"(d[1]), "+f"(d[2]), "+f"(d[3])
        : "r"(a[0]), "r"(a[1]), "r"(a[2]), "r"(a[3]), "r"(b[0]), "r"(b[1]));
}

// ---------------- edge scatter: agg[dst] += x[src] ---------------------------
__global__ void scatter_kernel(const float* __restrict__ x,
                               const int* __restrict__ src,
                               const int* __restrict__ dst,
                               float* __restrict__ agg, int nEdges) {
    int gid  = blockIdx.x * blockDim.x + threadIdx.x;
    int e    = gid >> 5;
    int lane = gid & 31;
    if (e >= nEdges) return;
    int s = src[e];
    int d = dst[e];
    float4 v = ((const float4*)x)[s * (D / 4) + lane];
    red_add_v4(((float4*)agg) + d * (D / 4) + lane, v);
}

// ---------------- weight prep: transpose + tf32 round ------------------------
__global__ void wprep_kernel(const float* __restrict__ W1, const float* __restrict__ W2,
                             float* __restrict__ w1t, float* __restrict__ w2t) {
    __shared__ float tile[32][33];
    int z = blockIdx.z;
    const float* src = (z < 3) ? (W1 + z * D * D) : (W2 + (z - 3) * D * D);
    float*       dstp = (z < 3) ? (w1t + z * D * D) : (w2t + (z - 3) * D * D);
    int x0 = blockIdx.x * 32, y0 = blockIdx.y * 32;
    int tx = threadIdx.x, ty = threadIdx.y;
    #pragma unroll
    for (int j = 0; j < 4; j++)
        tile[ty + j * 8][tx] = src[(y0 + ty + j * 8) * D + x0 + tx];
    __syncthreads();
    #pragma unroll
    for (int j = 0; j < 4; j++)
        dstp[(x0 + ty + j * 8) * D + y0 + tx] = tf32r(tile[tx][ty + j * 8]);
}

// ---------------- fused MLP layer on mma.sync tf32 ----------------------------
// smem: A[128][132] | B[128][132] | params (5 x 128 floats)
#define LDS_STRIDE 132
#define TILE_FLOATS (128 * LDS_STRIDE)
#define P_FLOATS (5 * 128)
#define SMEM_TOTAL_MLP ((2 * TILE_FLOATS + P_FLOATS) * 4)

__global__ __launch_bounds__(256, 1)
void mlp_mma_kernel(const float* __restrict__ xin,
                    const float* __restrict__ agg,
                    const float* __restrict__ w1t, const float* __restrict__ b1,
                    const float* __restrict__ w2t, const float* __restrict__ b2,
                    const float* __restrict__ bns, const float* __restrict__ bnb,
                    const float* __restrict__ bnm, const float* __restrict__ bnv,
                    float* __restrict__ xout, int nNodes) {
    extern __shared__ float smem[];
    float* As  = smem;                    // [128][132]
    float* Bs  = smem + TILE_FLOATS;      // [128][132]
    float* sb1 = smem + 2 * TILE_FLOATS;
    float* sb2 = sb1 + 128;
    float* skk = sb2 + 128;
    float* smm = skk + 128;
    float* scc = smm + 128;

    int tid  = threadIdx.x;
    int wid  = tid >> 5;
    int lane = tid & 31;
    int mg   = wid >> 1;        // 0..3   (m-group: rows mg*32 .. +31)
    int ng   = wid & 1;         // 0..1   (n-group: cols ng*64 .. +63)
    int gp   = lane >> 2;       // 0..7
    int tq   = lane & 3;        // 0..3
    int row0 = blockIdx.x * 128;

    if (tid < 128) {
        sb1[tid] = b1[tid];
        sb2[tid] = b2[tid];
        skk[tid] = bns[tid] * rsqrtf(bnv[tid] + BN_EPS);
        smm[tid] = bnm[tid];
        scc[tid] = bnb[tid];
    }

    // ---- load A (H = tf32(x+agg)) and B (W1T) -------------------------------
    const float4* x4  = (const float4*)xin;
    const float4* a4  = (const float4*)agg;
    const float4* w14 = (const float4*)w1t;
    for (int i = tid; i < 128 * 32; i += 256) {
        int row = i >> 5, c4 = i & 31;
        int gr = row0 + row;
        float4 hv = make_float4(0.f, 0.f, 0.f, 0.f);
        if (gr < nNodes) {
            float4 xv = x4[gr * 32 + c4];
            float4 av = a4[gr * 32 + c4];
            hv.x = tf32r(xv.x + av.x);
            hv.y = tf32r(xv.y + av.y);
            hv.z = tf32r(xv.z + av.z);
            hv.w = tf32r(xv.w + av.w);
        }
        *(float4*)(As + row * LDS_STRIDE + c4 * 4) = hv;
        *(float4*)(Bs + row * LDS_STRIDE + c4 * 4) = w14[i];
    }
    __syncthreads();

    float acc[2][8][4];
    #pragma unroll
    for (int mi = 0; mi < 2; mi++)
        #pragma unroll
        for (int ni = 0; ni < 8; ni++)
            #pragma unroll
            for (int c = 0; c < 4; c++) acc[mi][ni][c] = 0.f;

    // ---- GEMM 1: T = H @ W1 -------------------------------------------------
    #pragma unroll
    for (int s = 0; s < 16; s++) {
        int k0 = s * 8;
        uint32_t afr[2][4], bfr[8][2];
        #pragma unroll
        for (int mi = 0; mi < 2; mi++) {
            const float* ap = As + (mg * 32 + mi * 16 + gp) * LDS_STRIDE + k0 + tq;
            afr[mi][0] = __float_as_uint(ap[0]);
            afr[mi][1] = __float_as_uint(ap[8 * LDS_STRIDE]);
            afr[mi][2] = __float_as_uint(ap[4]);
            afr[mi][3] = __float_as_uint(ap[8 * LDS_STRIDE + 4]);
        }
        #pragma unroll
        for (int ni = 0; ni < 8; ni++) {
            const float* bp = Bs + (ng * 64 + ni * 8 + gp) * LDS_STRIDE + k0 + tq;
            bfr[ni][0] = __float_as_uint(bp[0]);
            bfr[ni][1] = __float_as_uint(bp[4]);
        }
        #pragma unroll
        for (int mi = 0; mi < 2; mi++)
            #pragma unroll
            for (int ni = 0; ni < 8; ni++)
                mma_tf32(acc[mi][ni], afr[mi], bfr[ni]);
    }
    __syncthreads();   // everyone done reading As/Bs

    // ---- epilogue 1: T = tf32(relu(y + b1)) -> As ---------------------------
    #pragma unroll
    for (int mi = 0; mi < 2; mi++) {
        #pragma unroll
        for (int ni = 0; ni < 8; ni++) {
            int col = ng * 64 + ni * 8 + tq * 2;
            int r0  = mg * 32 + mi * 16 + gp;
            float t0 = acc[mi][ni][0] + sb1[col];
            float t1 = acc[mi][ni][1] + sb1[col + 1];
            float t2 = acc[mi][ni][2] + sb1[col];
            float t3 = acc[mi][ni][3] + sb1[col + 1];
            float2 v01 = make_float2(tf32r(t0 > 0.f ? t0 : 0.f), tf32r(t1 > 0.f ? t1 : 0.f));
            float2 v23 = make_float2(tf32r(t2 > 0.f ? t2 : 0.f), tf32r(t3 > 0.f ? t3 : 0.f));
            *(float2*)(As + r0 * LDS_STRIDE + col)       = v01;
            *(float2*)(As + (r0 + 8) * LDS_STRIDE + col) = v23;
            // reset accumulators for GEMM 2
            acc[mi][ni][0] = 0.f; acc[mi][ni][1] = 0.f;
            acc[mi][ni][2] = 0.f; acc[mi][ni][3] = 0.f;
        }
    }
    // load W2T into Bs
    {
        const float4* w24 = (const float4*)w2t;
        for (int i = tid; i < 128 * 32; i += 256) {
            int row = i >> 5, c4 = i & 31;
            *(float4*)(Bs + row * LDS_STRIDE + c4 * 4) = w24[i];
        }
    }
    __syncthreads();

    // ---- GEMM 2: Y = T @ W2 -------------------------------------------------
    #pragma unroll
    for (int s = 0; s < 16; s++) {
        int k0 = s * 8;
        uint32_t afr[2][4], bfr[8][2];
        #pragma unroll
        for (int mi = 0; mi < 2; mi++) {
            const float* ap = As + (mg * 32 + mi * 16 + gp) * LDS_STRIDE + k0 + tq;
            afr[mi][0] = __float_as_uint(ap[0]);
            afr[mi][1] = __float_as_uint(ap[8 * LDS_STRIDE]);
            afr[mi][2] = __float_as_uint(ap[4]);
            afr[mi][3] = __float_as_uint(ap[8 * LDS_STRIDE + 4]);
        }
        #pragma unroll
        for (int ni = 0; ni < 8; ni++) {
            const float* bp = Bs + (ng * 64 + ni * 8 + gp) * LDS_STRIDE + k0 + tq;
            bfr[ni][0] = __float_as_uint(bp[0]);
            bfr[ni][1] = __float_as_uint(bp[4]);
        }
        #pragma unroll
        for (int mi = 0; mi < 2; mi++)
            #pragma unroll
            for (int ni = 0; ni < 8; ni++)
                mma_tf32(acc[mi][ni], afr[mi], bfr[ni]);
    }

    // ---- epilogue 2: bias + BN + relu -> gmem -------------------------------
    #pragma unroll
    for (int mi = 0; mi < 2; mi++) {
        #pragma unroll
        for (int ni = 0; ni < 8; ni++) {
            int col = ng * 64 + ni * 8 + tq * 2;
            int r0  = mg * 32 + mi * 16 + gp;
            int gr0 = row0 + r0;
            int gr1 = gr0 + 8;
            float kk0 = skk[col], kk1 = skk[col + 1];
            float t;
            if (gr0 < nNodes) {
                float2 v;
                t = (acc[mi][ni][0] + sb2[col]     - smm[col])     * kk0 + scc[col];
                v.x = t > 0.f ? t : 0.f;
                t = (acc[mi][ni][1] + sb2[col + 1] - smm[col + 1]) * kk1 + scc[col + 1];
                v.y = t > 0.f ? t : 0.f;
                *(float2*)(xout + (size_t)gr0 * D + col) = v;
            }
            if (gr1 < nNodes) {
                float2 v;
                t = (acc[mi][ni][2] + sb2[col]     - smm[col])     * kk0 + scc[col];
                v.x = t > 0.f ? t : 0.f;
                t = (acc[mi][ni][3] + sb2[col + 1] - smm[col + 1]) * kk1 + scc[col + 1];
                v.y = t > 0.f ? t : 0.f;
                *(float2*)(xout + (size_t)gr1 * D + col) = v;
            }
        }
    }
}

// ---------------- graph pooling ----------------------------------------------
__global__ void pool_kernel(const float* __restrict__ x,
                            const int* __restrict__ batch,
                            float* __restrict__ pool, int nNodes) {
    int gid  = blockIdx.x * blockDim.x + threadIdx.x;
    int node = gid >> 5;
    int lane = gid & 31;
    if (node >= nNodes) return;
    int g = batch[node];
    float4 v = ((const float4*)x)[node * (D / 4) + lane];
    red_add_v4(((float4*)pool) + g * (D / 4) + lane, v);
}

// ---------------- head --------------------------------------------------------
#define HID 64
#define NCLS 12
__global__ void head_kernel(const float* __restrict__ pool,
                            const float* __restrict__ Wh1, const float* __restrict__ bh1,
                            const float* __restrict__ Wh2, const float* __restrict__ bh2,
                            float* __restrict__ out, int nGraphs) {
    __shared__ float sg[D];
    __shared__ float sh1[HID];
    int g = blockIdx.x;
    if (g >= nGraphs) return;
    int tid = threadIdx.x;  // 64 threads
    sg[tid]       = pool[g * D + tid];
    sg[tid + HID] = pool[g * D + tid + HID];
    __syncthreads();
    float a = bh1[tid];
    #pragma unroll 4
    for (int k = 0; k < D; k++) a += sg[k] * Wh1[k * HID + tid];
    sh1[tid] = a > 0.f ? a : 0.f;
    __syncthreads();
    if (tid < NCLS) {
        float o = bh2[tid];
        #pragma unroll
        for (int k = 0; k < HID; k++) o += sh1[k] * Wh2[k * NCLS + tid];
        out[g * NCLS + tid] = 1.f / (1.f + expf(-o));
    }
}

// ---------------- launcher ---------------------------------------------------
extern "C" void kernel_launch(void* const* d_in, const int* in_sizes, int n_in,
                              void* d_out, int out_size) {
    const float* x     = (const float*)d_in[0];
    const int*   ei    = (const int*)d_in[1];
    const int*   batch = (const int*)d_in[2];
    const float* W1    = (const float*)d_in[3];
    const float* b1    = (const float*)d_in[4];
    const float* W2    = (const float*)d_in[5];
    const float* b2    = (const float*)d_in[6];
    const float* bns   = (const float*)d_in[7];
    const float* bnb   = (const float*)d_in[8];
    const float* bnm   = (const float*)d_in[9];
    const float* bnv   = (const float*)d_in[10];
    const float* Wh1   = (const float*)d_in[11];
    const float* bh1   = (const float*)d_in[12];
    const float* Wh2   = (const float*)d_in[13];
    const float* bh2   = (const float*)d_in[14];
    float* out = (float*)d_out;

    int nNodes  = in_sizes[0] / D;
    int nEdges  = in_sizes[1] / 2;
    int nGraphs = out_size / NCLS;

    const int* src = ei;
    const int* dst = ei + nEdges;

    float *agg, *x1, *x2, *pool, *w1t, *w2t;
    cudaGetSymbolAddress((void**)&agg,  g_agg);
    cudaGetSymbolAddress((void**)&x1,   g_x1);
    cudaGetSymbolAddress((void**)&x2,   g_x2);
    cudaGetSymbolAddress((void**)&pool, g_pool);
    cudaGetSymbolAddress((void**)&w1t,  g_w1t);
    cudaGetSymbolAddress((void**)&w2t,  g_w2t);

    cudaFuncSetAttribute(mlp_mma_kernel, cudaFuncAttributeMaxDynamicSharedMemorySize,
                         SMEM_TOTAL_MLP);

    wprep_kernel<<<dim3(4, 4, 6), dim3(32, 8)>>>(W1, W2, w1t, w2t);

    int scatterBlocks = (nEdges * 32 + 255) / 256;
    int mlpBlocks     = (nNodes + 127) / 128;
    int poolBlocks    = (nNodes * 32 + 255) / 256;

    const float* xs[4] = { x, x1, x2, x1 };
    float*       xd[3] = { x1, x2, x1 };

    for (int l = 0; l < 3; l++) {
        cudaMemsetAsync(agg, 0, (size_t)nNodes * D * sizeof(float));
        scatter_kernel<<<scatterBlocks, 256>>>(xs[l], src, dst, agg, nEdges);
        mlp_mma_kernel<<<mlpBlocks, 256, SMEM_TOTAL_MLP>>>(
            xs[l], agg,
            w1t + l * D * D, b1 + l * D,
            w2t + l * D * D, b2 + l * D,
            bns + l * D, bnb + l * D, bnm + l * D, bnv + l * D,
            xd[l], nNodes);
    }

    cudaMemsetAsync(pool, 0, (size_t)nGraphs * D * sizeof(float));
    pool_kernel<<<poolBlocks, 256>>>(xs[3], batch, pool, nNodes);
    head_kernel<<<nGraphs, HID>>>(pool, Wh1, bh1, Wh2, bh2, out, nGraphs);
}